// round 16
// baseline (speedup 1.0000x reference)
#include <cuda_runtime.h>
#include <cuda_bf16.h>
#include <cuda_fp16.h>
#include <math.h>
#include <stdint.h>

#define TOK 4096
#define DM 1024
#define NH 16
#define DH 64
#define SEQ 2048

// ---------------- scratch (device globals) ---------------------------------
__device__ __half g_xnh[TOK * DM];             // LayerNorm output (f16)
__device__ __half g_qb[TOK * DM];
__device__ __half g_kb[TOK * DM];
__device__ __half g_vb[TOK * DM];
__device__ __half g_ogh[TOK * DM];             // gated attention output (f16)
__device__ __half g_wh[4][DM * DM];            // Wq,Wk,Wv,Wo in f16
__device__ float2 g_cs2[TOK];
__device__ float g_headT[TOK * NH];

// ---------------- helpers ---------------------------------------------------
__device__ __forceinline__ uint32_t s2u(const void* p) {
    uint32_t a;
    asm("{ .reg .u64 t; cvta.to.shared.u64 t, %1; cvt.u32.u64 %0, t; }"
        : "=r"(a) : "l"(p));
    return a;
}
__device__ __forceinline__ uint32_t pkhf(float a, float b) {   // lo=a, hi=b
    uint32_t r;
    asm("cvt.rn.f16x2.f32 %0, %1, %2;" : "=r"(r) : "f"(b), "f"(a));
    return r;
}
__device__ __forceinline__ uint32_t ex2h2(uint32_t x) {        // 2x f16 exp2
    uint32_t y;
    asm("ex2.approx.f16x2 %0, %1;" : "=r"(y) : "r"(x));
    return y;
}
__device__ __forceinline__ uint32_t h2mul(uint32_t a, uint32_t b) {
    uint32_t r;
    asm("mul.rn.f16x2 %0, %1, %2;" : "=r"(r) : "r"(a), "r"(b));
    return r;
}
#define SW(o) ((uint32_t)(o) ^ ((((uint32_t)(o)) >> 3) & 0x70))

#define CPA(dst, src) asm volatile( \
    "cp.async.cg.shared.global [%0], [%1], 16;" :: "r"(dst), "l"(src))
#define CPCOMMIT() asm volatile("cp.async.commit_group;" ::: "memory")
#define CPWAIT1() asm volatile("cp.async.wait_group 1;" ::: "memory")
#define CPWAIT0() asm volatile("cp.async.wait_group 0;" ::: "memory")

#define LDSM4(r, a) asm volatile( \
    "ldmatrix.sync.aligned.m8n8.x4.shared.b16 {%0,%1,%2,%3}, [%4];" \
    : "=r"((r)[0]), "=r"((r)[1]), "=r"((r)[2]), "=r"((r)[3]) : "r"(a))
#define LDSM2(r, a) asm volatile( \
    "ldmatrix.sync.aligned.m8n8.x2.shared.b16 {%0,%1}, [%2];" \
    : "=r"((r)[0]), "=r"((r)[1]) : "r"(a))
#define LDSM4T(r, a) asm volatile( \
    "ldmatrix.sync.aligned.m8n8.x4.trans.shared.b16 {%0,%1,%2,%3}, [%4];" \
    : "=r"((r)[0]), "=r"((r)[1]), "=r"((r)[2]), "=r"((r)[3]) : "r"(a))

__device__ __forceinline__ void mmaf16(uint32_t* d, const uint32_t* a,
                                       uint32_t b0, uint32_t b1) {
    asm volatile(
        "mma.sync.aligned.m16n8k16.row.col.f16.f16.f16.f16 "
        "{%0,%1}, {%2,%3,%4,%5}, {%6,%7}, {%0,%1};"
        : "+r"(d[0]), "+r"(d[1])
        : "r"(a[0]), "r"(a[1]), "r"(a[2]), "r"(a[3]), "r"(b0), "r"(b1));
}
__device__ __forceinline__ void mmaf16k8(uint32_t* d, const uint32_t* a,
                                         uint32_t b0) {
    asm volatile(
        "mma.sync.aligned.m16n8k8.row.col.f16.f16.f16.f16 "
        "{%0,%1}, {%2,%3}, {%4}, {%0,%1};"
        : "+r"(d[0]), "+r"(d[1])
        : "r"(a[0]), "r"(a[1]), "r"(b0));
}
__device__ __forceinline__ void mmaf16f32(float* d, const uint32_t* a,
                                          uint32_t b0, uint32_t b1) {
    asm volatile(
        "mma.sync.aligned.m16n8k16.row.col.f32.f16.f16.f32 "
        "{%0,%1,%2,%3}, {%4,%5,%6,%7}, {%8,%9}, {%0,%1,%2,%3};"
        : "+f"(d[0]), "+f"(d[1]), "+f"(d[2]), "+f"(d[3])
        : "r"(a[0]), "r"(a[1]), "r"(a[2]), "r"(a[3]), "r"(b0), "r"(b1));
}

// ---------------- kernel 1: fused LayerNorm+phase+gates AND weight conv ----
__global__ __launch_bounds__(256) void prep_kernel(
    const float* __restrict__ x, const float* __restrict__ gamma,
    const float* __restrict__ beta, const float* __restrict__ Wp,
    const float* __restrict__ carrier, float* __restrict__ energy_slot,
    const float* __restrict__ W0, const float* __restrict__ W1,
    const float* __restrict__ W2, const float* __restrict__ W3)
{
    int tid = threadIdx.x;
    if (blockIdx.x >= TOK) {
        int gid = (blockIdx.x - TOK) * 256 + tid;   // float4 slot
        int a = gid >> 18, r = gid & 0x3FFFF;
        const float* src = (a == 0) ? W0 : (a == 1) ? W1 : (a == 2) ? W2 : W3;
        float4 v = ((const float4*)src)[r];
        uint32_t* d = (uint32_t*)(&g_wh[a][0] + (size_t)r * 4);
        d[0] = pkhf(v.x, v.y);
        d[1] = pkhf(v.z, v.w);
        return;
    }
    int row = blockIdx.x;
    __shared__ float red[16];
    __shared__ float bc[2];

    float4 v = ((const float4*)(x + (size_t)row * DM))[tid];
    float s  = v.x + v.y + v.z + v.w;
    float ss = v.x * v.x + v.y * v.y + v.z * v.z + v.w * v.w;
#pragma unroll
    for (int o = 16; o; o >>= 1) {
        s  += __shfl_xor_sync(0xffffffffu, s, o);
        ss += __shfl_xor_sync(0xffffffffu, ss, o);
    }
    int warp = tid >> 5, lane = tid & 31;
    if (lane == 0) { red[warp] = s; red[warp + 8] = ss; }
    __syncthreads();
    if (tid == 0) {
        float a = 0.f, b = 0.f;
#pragma unroll
        for (int i = 0; i < 8; i++) { a += red[i]; b += red[i + 8]; }
        float mu  = a * (1.0f / DM);
        float var = b * (1.0f / DM) - mu * mu;
        bc[0] = mu; bc[1] = rsqrtf(var + 1e-5f);
    }
    __syncthreads();
    float mu = bc[0], rstd = bc[1];

    float4 g  = ((const float4*)gamma)[tid];
    float4 be = ((const float4*)beta)[tid];
    float4 xv;
    xv.x = (v.x - mu) * rstd * g.x + be.x;
    xv.y = (v.y - mu) * rstd * g.y + be.y;
    xv.z = (v.z - mu) * rstd * g.z + be.z;
    xv.w = (v.w - mu) * rstd * g.w + be.w;
    uint32_t* dst = (uint32_t*)(g_xnh + (size_t)row * DM + tid * 4);
    dst[0] = pkhf(xv.x, xv.y);
    dst[1] = pkhf(xv.z, xv.w);

    float4 w = ((const float4*)Wp)[tid];
    float p = xv.x * w.x + xv.y * w.y + xv.z * w.z + xv.w * w.w;
#pragma unroll
    for (int o = 16; o; o >>= 1) p += __shfl_xor_sync(0xffffffffu, p, o);
    __syncthreads();
    if (lane == 0) red[warp] = p;
    __syncthreads();
    if (tid == 0) {
        float a = 0.f;
#pragma unroll
        for (int i = 0; i < 8; i++) a += red[i];
        bc[0] = a;
    }
    __syncthreads();
    float phase = bc[0];
    if (tid == 0) g_cs2[row] = make_float2(cosf(phase), sinf(phase));
    if (tid < NH) {
        float c = cosf((phase - carrier[tid]) * 0.5f);
        g_headT[row * NH + tid] = c * c;
    }
    if (row == 0 && tid == 0) *energy_slot = 0.f;
}

// ---------------- kernel 2: merged QKV projection ---------------------------
// z=0: fused Q+K (f16 acc, one A + two W tiles/chunk); z=1: V (f32 acc).
__global__ __launch_bounds__(256, 2) void gemm_qkv(void)
{
    extern __shared__ char smraw[];
    uint32_t sb = s2u(smraw);
    int tid = threadIdx.x, lane = tid & 31, w = tid >> 5;
    int wm = w & 3, wn = w >> 2;           // 4 warps in M, 2 in N
    int bm = blockIdx.y * 128, bn = blockIdx.x * 128;
    int lch = lane >> 4;

    if (blockIdx.z == 0) {
        // ---------- fused Q+K, f16 accumulators ----------
        const __half* A  = g_xnh;
        const __half* Wq = g_wh[0];
        const __half* Wk = g_wh[1];

        uint32_t accq[2][8][2], acck[2][8][2];
#pragma unroll
        for (int rs = 0; rs < 2; rs++)
#pragma unroll
            for (int j = 0; j < 8; j++) {
                accq[rs][j][0] = 0; accq[rs][j][1] = 0;
                acck[rs][j][0] = 0; acck[rs][j][1] = 0;
            }

        {
#pragma unroll
            for (int it = 0; it < 4; it++) {
                int i = tid + it * 256;
                int row = i >> 3, ch = i & 7;
                uint32_t so = SW(row * 128 + ch * 16);
                CPA(sb + so,         A  + (size_t)(bm + row) * DM + ch * 8);
                CPA(sb + 32768 + so, Wq + (size_t)(bn + row) * DM + ch * 8);
                CPA(sb + 65536 + so, Wk + (size_t)(bn + row) * DM + ch * 8);
            }
            CPCOMMIT();
        }

        for (int c = 0; c < 16; c++) {
            int buf = c & 1;
            if (c < 15) {
#pragma unroll
                for (int it = 0; it < 4; it++) {
                    int i = tid + it * 256;
                    int row = i >> 3, ch = i & 7;
                    uint32_t so = SW(row * 128 + ch * 16) + (buf ^ 1) * 16384;
                    CPA(sb + so,
                        A + (size_t)(bm + row) * DM + (c + 1) * 64 + ch * 8);
                    CPA(sb + 32768 + so,
                        Wq + (size_t)(bn + row) * DM + (c + 1) * 64 + ch * 8);
                    CPA(sb + 65536 + so,
                        Wk + (size_t)(bn + row) * DM + (c + 1) * 64 + ch * 8);
                }
                CPCOMMIT();
                CPWAIT1();
            } else {
                CPWAIT0();
            }
            __syncthreads();

            uint32_t ab  = sb + buf * 16384;
            uint32_t wqb = sb + 32768 + buf * 16384;
            uint32_t wkb = sb + 65536 + buf * 16384;
#pragma unroll
            for (int ks = 0; ks < 4; ks++) {
                uint32_t a[2][4];
#pragma unroll
                for (int rs = 0; rs < 2; rs++)
                    LDSM4(a[rs], ab + SW((wm * 32 + rs * 16 + (lane & 15)) * 128 +
                                         (ks * 2 + lch) * 16));
#pragma unroll
                for (int nb = 0; nb < 4; nb++) {
                    uint32_t bq[4], bk[4];
                    uint32_t rowoff = SW((wn * 64 + nb * 16 + (lane & 15)) * 128 +
                                         (ks * 2 + lch) * 16);
                    LDSM4(bq, wqb + rowoff);
                    LDSM4(bk, wkb + rowoff);
                    mmaf16(accq[0][2 * nb],     a[0], bq[0], bq[2]);
                    mmaf16(accq[0][2 * nb + 1], a[0], bq[1], bq[3]);
                    mmaf16(accq[1][2 * nb],     a[1], bq[0], bq[2]);
                    mmaf16(accq[1][2 * nb + 1], a[1], bq[1], bq[3]);
                    mmaf16(acck[0][2 * nb],     a[0], bk[0], bk[2]);
                    mmaf16(acck[0][2 * nb + 1], a[0], bk[1], bk[3]);
                    mmaf16(acck[1][2 * nb],     a[1], bk[0], bk[2]);
                    mmaf16(acck[1][2 * nb + 1], a[1], bk[1], bk[3]);
                }
            }
            __syncthreads();
        }

        uint32_t qsc = pkhf(0.18033688f, 0.18033688f);  // 0.125*log2e
        int c0 = (lane & 3) * 2;
#pragma unroll
        for (int rs = 0; rs < 2; rs++) {
            int m0 = bm + wm * 32 + rs * 16 + (lane >> 2);
#pragma unroll
            for (int j = 0; j < 8; j++) {
                int n = bn + wn * 64 + j * 8 + c0;
                *(uint32_t*)(g_qb + (size_t)m0 * DM + n) = h2mul(accq[rs][j][0], qsc);
                *(uint32_t*)(g_qb + (size_t)(m0 + 8) * DM + n) = h2mul(accq[rs][j][1], qsc);
                *(uint32_t*)(g_kb + (size_t)m0 * DM + n) = acck[rs][j][0];
                *(uint32_t*)(g_kb + (size_t)(m0 + 8) * DM + n) = acck[rs][j][1];
            }
        }
    } else {
        // ---------- V projection, f32 accumulators ----------
        const __half* A = g_xnh;
        const __half* W = g_wh[2];
        uint32_t As[2] = {sb, sb + 16384};
        uint32_t Ws[2] = {sb + 32768, sb + 49152};

        float acc[2][8][4];
#pragma unroll
        for (int rs = 0; rs < 2; rs++)
#pragma unroll
            for (int j = 0; j < 8; j++)
#pragma unroll
                for (int q = 0; q < 4; q++) acc[rs][j][q] = 0.f;

        {
#pragma unroll
            for (int it = 0; it < 4; it++) {
                int i = tid + it * 256;
                int row = i >> 3, ch = i & 7;
                uint32_t so = SW(row * 128 + ch * 16);
                CPA(As[0] + so, A + (size_t)(bm + row) * DM + ch * 8);
                CPA(Ws[0] + so, W + (size_t)(bn + row) * DM + ch * 8);
            }
            CPCOMMIT();
        }

        for (int c = 0; c < 16; c++) {
            int buf = c & 1;
            if (c < 15) {
#pragma unroll
                for (int it = 0; it < 4; it++) {
                    int i = tid + it * 256;
                    int row = i >> 3, ch = i & 7;
                    uint32_t so = SW(row * 128 + ch * 16);
                    CPA(As[buf ^ 1] + so,
                        A + (size_t)(bm + row) * DM + (c + 1) * 64 + ch * 8);
                    CPA(Ws[buf ^ 1] + so,
                        W + (size_t)(bn + row) * DM + (c + 1) * 64 + ch * 8);
                }
                CPCOMMIT();
                CPWAIT1();
            } else {
                CPWAIT0();
            }
            __syncthreads();

            uint32_t ab = As[buf], wb = Ws[buf];
#pragma unroll
            for (int ks = 0; ks < 4; ks++) {
                uint32_t a[2][4];
#pragma unroll
                for (int rs = 0; rs < 2; rs++)
                    LDSM4(a[rs], ab + SW((wm * 32 + rs * 16 + (lane & 15)) * 128 +
                                         (ks * 2 + lch) * 16));
#pragma unroll
                for (int nb = 0; nb < 4; nb++) {
                    uint32_t b[4];
                    LDSM4(b, wb + SW((wn * 64 + nb * 16 + (lane & 15)) * 128 +
                                     (ks * 2 + lch) * 16));
                    mmaf16f32(acc[0][2 * nb], a[0], b[0], b[2]);
                    mmaf16f32(acc[0][2 * nb + 1], a[0], b[1], b[3]);
                    mmaf16f32(acc[1][2 * nb], a[1], b[0], b[2]);
                    mmaf16f32(acc[1][2 * nb + 1], a[1], b[1], b[3]);
                }
            }
            __syncthreads();
        }

        int c0 = (lane & 3) * 2;
#pragma unroll
        for (int rs = 0; rs < 2; rs++) {
            int m0 = bm + wm * 32 + rs * 16 + (lane >> 2);
#pragma unroll
            for (int j = 0; j < 8; j++) {
                int n = bn + wn * 64 + j * 8 + c0;
                *(uint32_t*)(g_vb + (size_t)m0 * DM + n) =
                    pkhf(acc[rs][j][0], acc[rs][j][1]);
                *(uint32_t*)(g_vb + (size_t)(m0 + 8) * DM + n) =
                    pkhf(acc[rs][j][2], acc[rs][j][3]);
            }
        }
    }
}

// ---------------- kernel 2b: out-projection, 128x64 tiles (512 CTAs) -------
// grid (16,32); 3 CTAs/SM. Each warp 32(M)x32(N), f32 acc + residual.
__global__ __launch_bounds__(256, 3) void gemm_out(
    const float* __restrict__ xres, float* __restrict__ outf)
{
    extern __shared__ char smraw[];
    uint32_t sb = s2u(smraw);
    int tid = threadIdx.x, lane = tid & 31, w = tid >> 5;
    int wm = w & 3, wn = w >> 2;           // 4 warps in M, 2 in N (32 cols each)
    const __half* A = g_ogh;
    const __half* W = g_wh[3];
    int bm = blockIdx.y * 128, bn = blockIdx.x * 64;
    uint32_t As[2] = {sb, sb + 16384};
    uint32_t Ws[2] = {sb + 32768, sb + 40960};   // 8KB W stages

    float acc[2][4][4];
#pragma unroll
    for (int rs = 0; rs < 2; rs++)
#pragma unroll
        for (int j = 0; j < 4; j++)
#pragma unroll
            for (int q = 0; q < 4; q++) acc[rs][j][q] = 0.f;

    {
#pragma unroll
        for (int it = 0; it < 4; it++) {
            int i = tid + it * 256;
            int row = i >> 3, ch = i & 7;
            CPA(As[0] + SW(row * 128 + ch * 16),
                A + (size_t)(bm + row) * DM + ch * 8);
        }
#pragma unroll
        for (int it = 0; it < 2; it++) {
            int i = tid + it * 256;
            int row = i >> 3, ch = i & 7;
            CPA(Ws[0] + SW(row * 128 + ch * 16),
                W + (size_t)(bn + row) * DM + ch * 8);
        }
        CPCOMMIT();
    }

    for (int c = 0; c < 16; c++) {
        int buf = c & 1;
        if (c < 15) {
#pragma unroll
            for (int it = 0; it < 4; it++) {
                int i = tid + it * 256;
                int row = i >> 3, ch = i & 7;
                CPA(As[buf ^ 1] + SW(row * 128 + ch * 16),
                    A + (size_t)(bm + row) * DM + (c + 1) * 64 + ch * 8);
            }
#pragma unroll
            for (int it = 0; it < 2; it++) {
                int i = tid + it * 256;
                int row = i >> 3, ch = i & 7;
                CPA(Ws[buf ^ 1] + SW(row * 128 + ch * 16),
                    W + (size_t)(bn + row) * DM + (c + 1) * 64 + ch * 8);
            }
            CPCOMMIT();
            CPWAIT1();
        } else {
            CPWAIT0();
        }
        __syncthreads();

        uint32_t ab = As[buf], wb = Ws[buf];
        int lch = lane >> 4;
#pragma unroll
        for (int ks = 0; ks < 4; ks++) {
            uint32_t a[2][4];
#pragma unroll
            for (int rs = 0; rs < 2; rs++)
                LDSM4(a[rs], ab + SW((wm * 32 + rs * 16 + (lane & 15)) * 128 +
                                     (ks * 2 + lch) * 16));
#pragma unroll
            for (int nb = 0; nb < 2; nb++) {
                uint32_t b[4];
                LDSM4(b, wb + SW((wn * 32 + nb * 16 + (lane & 15)) * 128 +
                                 (ks * 2 + lch) * 16));
                mmaf16f32(acc[0][2 * nb], a[0], b[0], b[2]);
                mmaf16f32(acc[0][2 * nb + 1], a[0], b[1], b[3]);
                mmaf16f32(acc[1][2 * nb], a[1], b[0], b[2]);
                mmaf16f32(acc[1][2 * nb + 1], a[1], b[1], b[3]);
            }
        }
        __syncthreads();
    }

    int c0 = (lane & 3) * 2;
#pragma unroll
    for (int rs = 0; rs < 2; rs++) {
        int m0 = bm + wm * 32 + rs * 16 + (lane >> 2);
#pragma unroll
        for (int j = 0; j < 4; j++) {
            int n = bn + wn * 32 + j * 8 + c0;
            float2 x0 = *(const float2*)(xres + (size_t)m0 * DM + n);
            float2 x1 = *(const float2*)(xres + (size_t)(m0 + 8) * DM + n);
            float2 o0 = make_float2(acc[rs][j][0] + x0.x, acc[rs][j][1] + x0.y);
            float2 o1 = make_float2(acc[rs][j][2] + x1.x, acc[rs][j][3] + x1.y);
            *(float2*)(outf + (size_t)m0 * DM + n) = o0;
            *(float2*)(outf + (size_t)(m0 + 8) * DM + n) = o1;
        }
    }
}

// ---------------- kernel 3: HMMA flash attention (all-f16 softmax path) ----
#define AK0 0
#define AV0 16384
#define AK1 32768      /* Q parked here initially */
#define AV1 49152      /* CQ parked here initially (2KB used) */
#define ACK0 65536
#define ACK1 67584
#define ARED 69632
#define ASMEM 69760

__global__ __launch_bounds__(128, 3) void attn_hmma(
    const float* __restrict__ lam_ptr, float* __restrict__ energy)
{
    extern __shared__ char smraw[];
    uint32_t sb = s2u(smraw);
    int tid = threadIdx.x, lane = tid & 31, w = tid >> 5;   // w: 0..3
    int bh = blockIdx.y;
    int h = bh & (NH - 1);
    int T0 = (bh >> 4) * SEQ;
    int q0 = blockIdx.x * 128;
    float laml2 = 0.5f * (*lam_ptr) * 1.44269504f;

    uint32_t Ks[2]  = {sb + AK0, sb + AK1};
    uint32_t Vs[2]  = {sb + AV0, sb + AV1};
    uint32_t CKs[2] = {sb + ACK0, sb + ACK1};
    uint32_t one_b = (lane < 4) ? 0x3C003C00u : 0u;   // f16 ones col (n=0)

    // prologue: Q -> AK1, K0 -> AK0, V0 -> AV0 (one cp.async group)
#pragma unroll
    for (int it = 0; it < 8; it++) {
        int i = tid + it * 128;
        int row = i >> 3, ch = i & 7;
        uint32_t so = SW(row * 128 + ch * 16);
        CPA(sb + AK1 + so, g_qb + (size_t)(T0 + q0 + row) * DM + h * DH + ch * 8);
        CPA(sb + AK0 + so, g_kb + (size_t)(T0 + row) * DM + h * DH + ch * 8);
        CPA(sb + AV0 + so, g_vb + (size_t)(T0 + row) * DM + h * DH + ch * 8);
    }
    CPCOMMIT();
    {   // CQ (f16, lam-scaled, 16B/row) into AV1 area; CK0 (f16)
        float2 cq = g_cs2[T0 + q0 + tid];
        uint32_t* d = (uint32_t*)(smraw + AV1 + tid * 16);
        d[0] = pkhf(laml2 * cq.x, laml2 * cq.y);
        d[1] = pkhf(laml2, 0.f);
        d[2] = 0; d[3] = 0;
        float2 ck = g_cs2[T0 + tid];
        uint32_t* e = (uint32_t*)(smraw + ACK0 + tid * 16);
        e[0] = pkhf(ck.x, ck.y);
        e[1] = pkhf(1.f, 0.f);
        e[2] = 0; e[3] = 0;
    }
    CPWAIT0();
    __syncthreads();

    // Q (k16 x4) + CQ (k8 x2) fragments for both 16-row sets
    uint32_t qf[2][4][4];
    uint32_t qfr[2][2];
    {
        int lch = lane >> 4;
#pragma unroll
        for (int rs = 0; rs < 2; rs++) {
            int arow = w * 32 + rs * 16 + (lane & 15);
#pragma unroll
            for (int ks = 0; ks < 4; ks++)
                LDSM4(qf[rs][ks], sb + AK1 + SW(arow * 128 + (ks * 2 + lch) * 16));
            LDSM2(qfr[rs], sb + AV1 + arow * 16);
        }
    }
    __syncthreads();   // everyone done with Q/CQ before buf1 prefetch clobbers

    uint32_t oacc[2][8][2];
#pragma unroll
    for (int rs = 0; rs < 2; rs++)
#pragma unroll
        for (int j = 0; j < 8; j++) { oacc[rs][j][0] = 0; oacc[rs][j][1] = 0; }
    float lpacc[2][4];
#pragma unroll
    for (int rs = 0; rs < 2; rs++)
#pragma unroll
        for (int q = 0; q < 4; q++) lpacc[rs][q] = 0.f;

    for (int t = 0; t < 16; t++) {
        int buf = t & 1;
        if (t < 15) {
#pragma unroll
            for (int it = 0; it < 8; it++) {
                int i = tid + it * 128;
                int row = i >> 3, ch = i & 7;
                uint32_t so = SW(row * 128 + ch * 16);
                CPA(Ks[buf ^ 1] + so,
                    g_kb + (size_t)(T0 + (t + 1) * 128 + row) * DM + h * DH + ch * 8);
                CPA(Vs[buf ^ 1] + so,
                    g_vb + (size_t)(T0 + (t + 1) * 128 + row) * DM + h * DH + ch * 8);
            }
            CPCOMMIT();
            {
                float2 cs = g_cs2[T0 + (t + 1) * 128 + tid];
                uint32_t* d = (uint32_t*)(smraw + (buf ? ACK0 : ACK1) + tid * 16);
                d[0] = pkhf(cs.x, cs.y);
                d[1] = pkhf(1.f, 0.f);
                d[2] = 0; d[3] = 0;
            }
            CPWAIT1();
        } else {
            CPWAIT0();
        }
        __syncthreads();

        int lch = lane >> 4;
#pragma unroll
        for (int t8 = 0; t8 < 8; t8++) {
            // f16x2 accumulators: [rs][n-half][row-pair]
            uint32_t sacc[2][2][2];
#pragma unroll
            for (int rs = 0; rs < 2; rs++) {
                sacc[rs][0][0] = 0; sacc[rs][0][1] = 0;
                sacc[rs][1][0] = 0; sacc[rs][1][1] = 0;
            }
#pragma unroll
            for (int ks = 0; ks < 4; ks++) {
                uint32_t b[4];
                LDSM4(b, Ks[buf] + SW((t8 * 16 + (lane & 15)) * 128 +
                                      (ks * 2 + lch) * 16));
                mmaf16(sacc[0][0], qf[0][ks], b[0], b[2]);
                mmaf16(sacc[0][1], qf[0][ks], b[1], b[3]);
                mmaf16(sacc[1][0], qf[1][ks], b[0], b[2]);
                mmaf16(sacc[1][1], qf[1][ks], b[1], b[3]);
            }
            {   // resonance k8 step (f16)
                uint32_t b[2];
                LDSM2(b, CKs[buf] + (t8 * 16 + (lane & 15)) * 16);
                mmaf16k8(sacc[0][0], qfr[0], b[0]);
                mmaf16k8(sacc[0][1], qfr[0], b[1]);
                mmaf16k8(sacc[1][0], qfr[1], b[0]);
                mmaf16k8(sacc[1][1], qfr[1], b[1]);
            }

            // exp2 directly on accumulator f16x2 regs -> PV A fragments
            uint32_t pa[2][4];
#pragma unroll
            for (int rs = 0; rs < 2; rs++) {
                pa[rs][0] = ex2h2(sacc[rs][0][0]);
                pa[rs][1] = ex2h2(sacc[rs][0][1]);
                pa[rs][2] = ex2h2(sacc[rs][1][0]);
                pa[rs][3] = ex2h2(sacc[rs][1][1]);
            }
            // softmax denominator via ones-column MMA (f32 acc)
            mmaf16f32(lpacc[0], pa[0], one_b, one_b);
            mmaf16f32(lpacc[1], pa[1], one_b, one_b);
#pragma unroll
            for (int jt = 0; jt < 4; jt++) {
                uint32_t b[4];
                LDSM4T(b, Vs[buf] + SW((t8 * 16 + (lane & 15)) * 128 +
                                       (2 * jt + lch) * 16));
                mmaf16(oacc[0][2 * jt], pa[0], b[0], b[1]);
                mmaf16(oacc[0][2 * jt + 1], pa[0], b[2], b[3]);
                mmaf16(oacc[1][2 * jt], pa[1], b[0], b[1]);
                mmaf16(oacc[1][2 * jt + 1], pa[1], b[2], b[3]);
            }
        }
        __syncthreads();
    }

    int c0 = (lane & 3) * 2;
    float es = 0.f;
#pragma unroll
    for (int rs = 0; rs < 2; rs++) {
        int r0g = T0 + q0 + w * 32 + rs * 16 + (lane >> 2);
        int r1g = r0g + 8;
        // lp lives in col0 of lpacc on quad leaders; broadcast within quad
        float l0 = __shfl_sync(0xffffffffu, lpacc[rs][0], lane & 28);
        float l1 = __shfl_sync(0xffffffffu, lpacc[rs][2], lane & 28);
        float inv0 = g_headT[r0g * NH + h] / l0;
        float inv1 = g_headT[r1g * NH + h] / l1;
#pragma unroll
        for (int jt = 0; jt < 8; jt++) {
            int d = h * DH + jt * 8 + c0;
            float2 f0 = __half22float2(*(__half2*)&oacc[rs][jt][0]);
            float2 f1 = __half22float2(*(__half2*)&oacc[rs][jt][1]);
            float o0 = f0.x * inv0, o1 = f0.y * inv0;
            float o2 = f1.x * inv1, o3 = f1.y * inv1;
            es += fabsf(o0) + fabsf(o1) + fabsf(o2) + fabsf(o3);
            *(uint32_t*)(g_ogh + (size_t)r0g * DM + d) = pkhf(o0, o1);
            *(uint32_t*)(g_ogh + (size_t)r1g * DM + d) = pkhf(o2, o3);
        }
    }
#pragma unroll
    for (int o = 16; o; o >>= 1) es += __shfl_xor_sync(0xffffffffu, es, o);
    float* red = (float*)(smraw + ARED);
    if (lane == 0) red[w] = es;
    __syncthreads();
    if (tid == 0) {
        float tsum = red[0] + red[1] + red[2] + red[3];
        atomicAdd(energy, tsum);
    }
}

// ---------------- launch ---------------------------------------------------
extern "C" void kernel_launch(void* const* d_in, const int* in_sizes, int n_in,
                              void* d_out, int out_size)
{
    const float* x       = (const float*)d_in[0];
    const float* Wq      = (const float*)d_in[1];
    const float* Wk      = (const float*)d_in[2];
    const float* Wv      = (const float*)d_in[3];
    const float* Wo      = (const float*)d_in[4];
    const float* Wp      = (const float*)d_in[5];
    const float* gamma   = (const float*)d_in[6];
    const float* beta    = (const float*)d_in[7];
    const float* carrier = (const float*)d_in[8];
    const float* lam     = (const float*)d_in[9];

    float* out    = (float*)d_out;
    float* energy = out + (out_size - 1);

    cudaFuncSetAttribute(gemm_qkv, cudaFuncAttributeMaxDynamicSharedMemorySize, 98304);
    cudaFuncSetAttribute(gemm_out, cudaFuncAttributeMaxDynamicSharedMemorySize, 49152);
    cudaFuncSetAttribute(attn_hmma, cudaFuncAttributeMaxDynamicSharedMemorySize, ASMEM);

    prep_kernel<<<2 * TOK, 256>>>(x, gamma, beta, Wp, carrier, energy,
                                  Wq, Wk, Wv, Wo);
    gemm_qkv<<<dim3(8, 32, 2), 256, 98304>>>();
    attn_hmma<<<dim3(SEQ / 128, 2 * NH), 128, ASMEM>>>(lam, energy);
    gemm_out<<<dim3(16, 32), 256, 49152>>>(x, out);
}

// round 17
// speedup vs baseline: 1.0292x; 1.0292x over previous
#include <cuda_runtime.h>
#include <cuda_bf16.h>
#include <cuda_fp16.h>
#include <math.h>
#include <stdint.h>

#define TOK 4096
#define DM 1024
#define NH 16
#define DH 64
#define SEQ 2048

// ---------------- scratch (device globals) ---------------------------------
__device__ __half g_xnh[TOK * DM];             // LayerNorm output (f16)
__device__ __half g_qb[TOK * DM];
__device__ __half g_kb[TOK * DM];
__device__ __half g_vb[TOK * DM];
__device__ __half g_ogh[TOK * DM];             // gated attention output (f16)
__device__ __half g_wh[4][DM * DM];            // Wq,Wk,Wv,Wo in f16
__device__ __half g_op[2 * TOK * DM];          // split-K partial O (f16)
__device__ float  g_lpg[2 * TOK * NH];         // split-K partial denominators
__device__ float2 g_cs2[TOK];
__device__ float g_headT[TOK * NH];

// ---------------- helpers ---------------------------------------------------
__device__ __forceinline__ uint32_t s2u(const void* p) {
    uint32_t a;
    asm("{ .reg .u64 t; cvta.to.shared.u64 t, %1; cvt.u32.u64 %0, t; }"
        : "=r"(a) : "l"(p));
    return a;
}
__device__ __forceinline__ uint32_t pkhf(float a, float b) {   // lo=a, hi=b
    uint32_t r;
    asm("cvt.rn.f16x2.f32 %0, %1, %2;" : "=r"(r) : "f"(b), "f"(a));
    return r;
}
__device__ __forceinline__ uint32_t ex2h2(uint32_t x) {        // 2x f16 exp2
    uint32_t y;
    asm("ex2.approx.f16x2 %0, %1;" : "=r"(y) : "r"(x));
    return y;
}
__device__ __forceinline__ uint32_t h2mul(uint32_t a, uint32_t b) {
    uint32_t r;
    asm("mul.rn.f16x2 %0, %1, %2;" : "=r"(r) : "r"(a), "r"(b));
    return r;
}
#define SW(o) ((uint32_t)(o) ^ ((((uint32_t)(o)) >> 3) & 0x70))

#define CPA(dst, src) asm volatile( \
    "cp.async.cg.shared.global [%0], [%1], 16;" :: "r"(dst), "l"(src))
#define CPCOMMIT() asm volatile("cp.async.commit_group;" ::: "memory")
#define CPWAIT1() asm volatile("cp.async.wait_group 1;" ::: "memory")
#define CPWAIT0() asm volatile("cp.async.wait_group 0;" ::: "memory")

#define LDSM4(r, a) asm volatile( \
    "ldmatrix.sync.aligned.m8n8.x4.shared.b16 {%0,%1,%2,%3}, [%4];" \
    : "=r"((r)[0]), "=r"((r)[1]), "=r"((r)[2]), "=r"((r)[3]) : "r"(a))
#define LDSM2(r, a) asm volatile( \
    "ldmatrix.sync.aligned.m8n8.x2.shared.b16 {%0,%1}, [%2];" \
    : "=r"((r)[0]), "=r"((r)[1]) : "r"(a))
#define LDSM4T(r, a) asm volatile( \
    "ldmatrix.sync.aligned.m8n8.x4.trans.shared.b16 {%0,%1,%2,%3}, [%4];" \
    : "=r"((r)[0]), "=r"((r)[1]), "=r"((r)[2]), "=r"((r)[3]) : "r"(a))

__device__ __forceinline__ void mmaf16(uint32_t* d, const uint32_t* a,
                                       uint32_t b0, uint32_t b1) {
    asm volatile(
        "mma.sync.aligned.m16n8k16.row.col.f16.f16.f16.f16 "
        "{%0,%1}, {%2,%3,%4,%5}, {%6,%7}, {%0,%1};"
        : "+r"(d[0]), "+r"(d[1])
        : "r"(a[0]), "r"(a[1]), "r"(a[2]), "r"(a[3]), "r"(b0), "r"(b1));
}
__device__ __forceinline__ void mmaf16k8(uint32_t* d, const uint32_t* a,
                                         uint32_t b0) {
    asm volatile(
        "mma.sync.aligned.m16n8k8.row.col.f16.f16.f16.f16 "
        "{%0,%1}, {%2,%3}, {%4}, {%0,%1};"
        : "+r"(d[0]), "+r"(d[1])
        : "r"(a[0]), "r"(a[1]), "r"(b0));
}
__device__ __forceinline__ void mmaf16f32(float* d, const uint32_t* a,
                                          uint32_t b0, uint32_t b1) {
    asm volatile(
        "mma.sync.aligned.m16n8k16.row.col.f32.f16.f16.f32 "
        "{%0,%1,%2,%3}, {%4,%5,%6,%7}, {%8,%9}, {%0,%1,%2,%3};"
        : "+f"(d[0]), "+f"(d[1]), "+f"(d[2]), "+f"(d[3])
        : "r"(a[0]), "r"(a[1]), "r"(a[2]), "r"(a[3]), "r"(b0), "r"(b1));
}

// ---------------- kernel 1: fused LayerNorm+phase+gates AND weight conv ----
__global__ __launch_bounds__(256) void prep_kernel(
    const float* __restrict__ x, const float* __restrict__ gamma,
    const float* __restrict__ beta, const float* __restrict__ Wp,
    const float* __restrict__ carrier, float* __restrict__ energy_slot,
    const float* __restrict__ W0, const float* __restrict__ W1,
    const float* __restrict__ W2, const float* __restrict__ W3)
{
    int tid = threadIdx.x;
    if (blockIdx.x >= TOK) {
        int gid = (blockIdx.x - TOK) * 256 + tid;   // float4 slot
        int a = gid >> 18, r = gid & 0x3FFFF;
        const float* src = (a == 0) ? W0 : (a == 1) ? W1 : (a == 2) ? W2 : W3;
        float4 v = ((const float4*)src)[r];
        uint32_t* d = (uint32_t*)(&g_wh[a][0] + (size_t)r * 4);
        d[0] = pkhf(v.x, v.y);
        d[1] = pkhf(v.z, v.w);
        return;
    }
    int row = blockIdx.x;
    __shared__ float red[16];
    __shared__ float bc[2];

    float4 v = ((const float4*)(x + (size_t)row * DM))[tid];
    float s  = v.x + v.y + v.z + v.w;
    float ss = v.x * v.x + v.y * v.y + v.z * v.z + v.w * v.w;
#pragma unroll
    for (int o = 16; o; o >>= 1) {
        s  += __shfl_xor_sync(0xffffffffu, s, o);
        ss += __shfl_xor_sync(0xffffffffu, ss, o);
    }
    int warp = tid >> 5, lane = tid & 31;
    if (lane == 0) { red[warp] = s; red[warp + 8] = ss; }
    __syncthreads();
    if (tid == 0) {
        float a = 0.f, b = 0.f;
#pragma unroll
        for (int i = 0; i < 8; i++) { a += red[i]; b += red[i + 8]; }
        float mu  = a * (1.0f / DM);
        float var = b * (1.0f / DM) - mu * mu;
        bc[0] = mu; bc[1] = rsqrtf(var + 1e-5f);
    }
    __syncthreads();
    float mu = bc[0], rstd = bc[1];

    float4 g  = ((const float4*)gamma)[tid];
    float4 be = ((const float4*)beta)[tid];
    float4 xv;
    xv.x = (v.x - mu) * rstd * g.x + be.x;
    xv.y = (v.y - mu) * rstd * g.y + be.y;
    xv.z = (v.z - mu) * rstd * g.z + be.z;
    xv.w = (v.w - mu) * rstd * g.w + be.w;
    uint32_t* dst = (uint32_t*)(g_xnh + (size_t)row * DM + tid * 4);
    dst[0] = pkhf(xv.x, xv.y);
    dst[1] = pkhf(xv.z, xv.w);

    float4 w = ((const float4*)Wp)[tid];
    float p = xv.x * w.x + xv.y * w.y + xv.z * w.z + xv.w * w.w;
#pragma unroll
    for (int o = 16; o; o >>= 1) p += __shfl_xor_sync(0xffffffffu, p, o);
    __syncthreads();
    if (lane == 0) red[warp] = p;
    __syncthreads();
    if (tid == 0) {
        float a = 0.f;
#pragma unroll
        for (int i = 0; i < 8; i++) a += red[i];
        bc[0] = a;
    }
    __syncthreads();
    float phase = bc[0];
    if (tid == 0) g_cs2[row] = make_float2(cosf(phase), sinf(phase));
    if (tid < NH) {
        float c = cosf((phase - carrier[tid]) * 0.5f);
        g_headT[row * NH + tid] = c * c;
    }
    if (row == 0 && tid == 0) *energy_slot = 0.f;
}

// ---------------- kernel 2: merged QKV projection ---------------------------
// z=0: fused Q+K (f16 acc); z=1: V (f32 acc). 512 CTAs, one launch.
__global__ __launch_bounds__(256, 2) void gemm_qkv(void)
{
    extern __shared__ char smraw[];
    uint32_t sb = s2u(smraw);
    int tid = threadIdx.x, lane = tid & 31, w = tid >> 5;
    int wm = w & 3, wn = w >> 2;           // 4 warps in M, 2 in N
    int bm = blockIdx.y * 128, bn = blockIdx.x * 128;
    int lch = lane >> 4;

    if (blockIdx.z == 0) {
        const __half* A  = g_xnh;
        const __half* Wq = g_wh[0];
        const __half* Wk = g_wh[1];

        uint32_t accq[2][8][2], acck[2][8][2];
#pragma unroll
        for (int rs = 0; rs < 2; rs++)
#pragma unroll
            for (int j = 0; j < 8; j++) {
                accq[rs][j][0] = 0; accq[rs][j][1] = 0;
                acck[rs][j][0] = 0; acck[rs][j][1] = 0;
            }

        {
#pragma unroll
            for (int it = 0; it < 4; it++) {
                int i = tid + it * 256;
                int row = i >> 3, ch = i & 7;
                uint32_t so = SW(row * 128 + ch * 16);
                CPA(sb + so,         A  + (size_t)(bm + row) * DM + ch * 8);
                CPA(sb + 32768 + so, Wq + (size_t)(bn + row) * DM + ch * 8);
                CPA(sb + 65536 + so, Wk + (size_t)(bn + row) * DM + ch * 8);
            }
            CPCOMMIT();
        }

        for (int c = 0; c < 16; c++) {
            int buf = c & 1;
            if (c < 15) {
#pragma unroll
                for (int it = 0; it < 4; it++) {
                    int i = tid + it * 256;
                    int row = i >> 3, ch = i & 7;
                    uint32_t so = SW(row * 128 + ch * 16) + (buf ^ 1) * 16384;
                    CPA(sb + so,
                        A + (size_t)(bm + row) * DM + (c + 1) * 64 + ch * 8);
                    CPA(sb + 32768 + so,
                        Wq + (size_t)(bn + row) * DM + (c + 1) * 64 + ch * 8);
                    CPA(sb + 65536 + so,
                        Wk + (size_t)(bn + row) * DM + (c + 1) * 64 + ch * 8);
                }
                CPCOMMIT();
                CPWAIT1();
            } else {
                CPWAIT0();
            }
            __syncthreads();

            uint32_t ab  = sb + buf * 16384;
            uint32_t wqb = sb + 32768 + buf * 16384;
            uint32_t wkb = sb + 65536 + buf * 16384;
#pragma unroll
            for (int ks = 0; ks < 4; ks++) {
                uint32_t a[2][4];
#pragma unroll
                for (int rs = 0; rs < 2; rs++)
                    LDSM4(a[rs], ab + SW((wm * 32 + rs * 16 + (lane & 15)) * 128 +
                                         (ks * 2 + lch) * 16));
#pragma unroll
                for (int nb = 0; nb < 4; nb++) {
                    uint32_t bq[4], bk[4];
                    uint32_t rowoff = SW((wn * 64 + nb * 16 + (lane & 15)) * 128 +
                                         (ks * 2 + lch) * 16);
                    LDSM4(bq, wqb + rowoff);
                    LDSM4(bk, wkb + rowoff);
                    mmaf16(accq[0][2 * nb],     a[0], bq[0], bq[2]);
                    mmaf16(accq[0][2 * nb + 1], a[0], bq[1], bq[3]);
                    mmaf16(accq[1][2 * nb],     a[1], bq[0], bq[2]);
                    mmaf16(accq[1][2 * nb + 1], a[1], bq[1], bq[3]);
                    mmaf16(acck[0][2 * nb],     a[0], bk[0], bk[2]);
                    mmaf16(acck[0][2 * nb + 1], a[0], bk[1], bk[3]);
                    mmaf16(acck[1][2 * nb],     a[1], bk[0], bk[2]);
                    mmaf16(acck[1][2 * nb + 1], a[1], bk[1], bk[3]);
                }
            }
            __syncthreads();
        }

        uint32_t qsc = pkhf(0.18033688f, 0.18033688f);  // 0.125*log2e
        int c0 = (lane & 3) * 2;
#pragma unroll
        for (int rs = 0; rs < 2; rs++) {
            int m0 = bm + wm * 32 + rs * 16 + (lane >> 2);
#pragma unroll
            for (int j = 0; j < 8; j++) {
                int n = bn + wn * 64 + j * 8 + c0;
                *(uint32_t*)(g_qb + (size_t)m0 * DM + n) = h2mul(accq[rs][j][0], qsc);
                *(uint32_t*)(g_qb + (size_t)(m0 + 8) * DM + n) = h2mul(accq[rs][j][1], qsc);
                *(uint32_t*)(g_kb + (size_t)m0 * DM + n) = acck[rs][j][0];
                *(uint32_t*)(g_kb + (size_t)(m0 + 8) * DM + n) = acck[rs][j][1];
            }
        }
    } else {
        const __half* A = g_xnh;
        const __half* W = g_wh[2];
        uint32_t As[2] = {sb, sb + 16384};
        uint32_t Ws[2] = {sb + 32768, sb + 49152};

        float acc[2][8][4];
#pragma unroll
        for (int rs = 0; rs < 2; rs++)
#pragma unroll
            for (int j = 0; j < 8; j++)
#pragma unroll
                for (int q = 0; q < 4; q++) acc[rs][j][q] = 0.f;

        {
#pragma unroll
            for (int it = 0; it < 4; it++) {
                int i = tid + it * 256;
                int row = i >> 3, ch = i & 7;
                uint32_t so = SW(row * 128 + ch * 16);
                CPA(As[0] + so, A + (size_t)(bm + row) * DM + ch * 8);
                CPA(Ws[0] + so, W + (size_t)(bn + row) * DM + ch * 8);
            }
            CPCOMMIT();
        }

        for (int c = 0; c < 16; c++) {
            int buf = c & 1;
            if (c < 15) {
#pragma unroll
                for (int it = 0; it < 4; it++) {
                    int i = tid + it * 256;
                    int row = i >> 3, ch = i & 7;
                    uint32_t so = SW(row * 128 + ch * 16);
                    CPA(As[buf ^ 1] + so,
                        A + (size_t)(bm + row) * DM + (c + 1) * 64 + ch * 8);
                    CPA(Ws[buf ^ 1] + so,
                        W + (size_t)(bn + row) * DM + (c + 1) * 64 + ch * 8);
                }
                CPCOMMIT();
                CPWAIT1();
            } else {
                CPWAIT0();
            }
            __syncthreads();

            uint32_t ab = As[buf], wb = Ws[buf];
#pragma unroll
            for (int ks = 0; ks < 4; ks++) {
                uint32_t a[2][4];
#pragma unroll
                for (int rs = 0; rs < 2; rs++)
                    LDSM4(a[rs], ab + SW((wm * 32 + rs * 16 + (lane & 15)) * 128 +
                                         (ks * 2 + lch) * 16));
#pragma unroll
                for (int nb = 0; nb < 4; nb++) {
                    uint32_t b[4];
                    LDSM4(b, wb + SW((wn * 64 + nb * 16 + (lane & 15)) * 128 +
                                     (ks * 2 + lch) * 16));
                    mmaf16f32(acc[0][2 * nb], a[0], b[0], b[2]);
                    mmaf16f32(acc[0][2 * nb + 1], a[0], b[1], b[3]);
                    mmaf16f32(acc[1][2 * nb], a[1], b[0], b[2]);
                    mmaf16f32(acc[1][2 * nb + 1], a[1], b[1], b[3]);
                }
            }
            __syncthreads();
        }

        int c0 = (lane & 3) * 2;
#pragma unroll
        for (int rs = 0; rs < 2; rs++) {
            int m0 = bm + wm * 32 + rs * 16 + (lane >> 2);
#pragma unroll
            for (int j = 0; j < 8; j++) {
                int n = bn + wn * 64 + j * 8 + c0;
                *(uint32_t*)(g_vb + (size_t)m0 * DM + n) =
                    pkhf(acc[rs][j][0], acc[rs][j][1]);
                *(uint32_t*)(g_vb + (size_t)(m0 + 8) * DM + n) =
                    pkhf(acc[rs][j][2], acc[rs][j][3]);
            }
        }
    }
}

// ---------------- kernel 2b: out-projection (R15 version: 128x128 tiles) ---
__global__ __launch_bounds__(256, 2) void gemm_out(
    const float* __restrict__ xres, float* __restrict__ outf)
{
    extern __shared__ char smraw[];
    uint32_t sb = s2u(smraw);
    int tid = threadIdx.x, lane = tid & 31, w = tid >> 5;
    int wm = w & 3, wn = w >> 2;
    const __half* A = g_ogh;
    const __half* W = g_wh[3];
    int bm = blockIdx.y * 128, bn = blockIdx.x * 128;
    uint32_t As[2] = {sb, sb + 16384};
    uint32_t Ws[2] = {sb + 32768, sb + 49152};

    float acc[2][8][4];
#pragma unroll
    for (int rs = 0; rs < 2; rs++)
#pragma unroll
        for (int j = 0; j < 8; j++)
#pragma unroll
            for (int q = 0; q < 4; q++) acc[rs][j][q] = 0.f;

    {
#pragma unroll
        for (int it = 0; it < 4; it++) {
            int i = tid + it * 256;
            int row = i >> 3, ch = i & 7;
            uint32_t so = SW(row * 128 + ch * 16);
            CPA(As[0] + so, A + (size_t)(bm + row) * DM + ch * 8);
            CPA(Ws[0] + so, W + (size_t)(bn + row) * DM + ch * 8);
        }
        CPCOMMIT();
    }

    for (int c = 0; c < 16; c++) {
        int buf = c & 1;
        if (c < 15) {
#pragma unroll
            for (int it = 0; it < 4; it++) {
                int i = tid + it * 256;
                int row = i >> 3, ch = i & 7;
                uint32_t so = SW(row * 128 + ch * 16);
                CPA(As[buf ^ 1] + so,
                    A + (size_t)(bm + row) * DM + (c + 1) * 64 + ch * 8);
                CPA(Ws[buf ^ 1] + so,
                    W + (size_t)(bn + row) * DM + (c + 1) * 64 + ch * 8);
            }
            CPCOMMIT();
            CPWAIT1();
        } else {
            CPWAIT0();
        }
        __syncthreads();

        uint32_t ab = As[buf], wb = Ws[buf];
        int lch = lane >> 4;
#pragma unroll
        for (int ks = 0; ks < 4; ks++) {
            uint32_t a[2][4];
#pragma unroll
            for (int rs = 0; rs < 2; rs++)
                LDSM4(a[rs], ab + SW((wm * 32 + rs * 16 + (lane & 15)) * 128 +
                                     (ks * 2 + lch) * 16));
#pragma unroll
            for (int nb = 0; nb < 4; nb++) {
                uint32_t b[4];
                LDSM4(b, wb + SW((wn * 64 + nb * 16 + (lane & 15)) * 128 +
                                 (ks * 2 + lch) * 16));
                mmaf16f32(acc[0][2 * nb], a[0], b[0], b[2]);
                mmaf16f32(acc[0][2 * nb + 1], a[0], b[1], b[3]);
                mmaf16f32(acc[1][2 * nb], a[1], b[0], b[2]);
                mmaf16f32(acc[1][2 * nb + 1], a[1], b[1], b[3]);
            }
        }
        __syncthreads();
    }

    int c0 = (lane & 3) * 2;
#pragma unroll
    for (int rs = 0; rs < 2; rs++) {
        int m0 = bm + wm * 32 + rs * 16 + (lane >> 2);
#pragma unroll
        for (int j = 0; j < 8; j++) {
            int n = bn + wn * 64 + j * 8 + c0;
            float2 x0 = *(const float2*)(xres + (size_t)m0 * DM + n);
            float2 x1 = *(const float2*)(xres + (size_t)(m0 + 8) * DM + n);
            float2 o0 = make_float2(acc[rs][j][0] + x0.x, acc[rs][j][1] + x0.y);
            float2 o1 = make_float2(acc[rs][j][2] + x1.x, acc[rs][j][3] + x1.y);
            *(float2*)(outf + (size_t)m0 * DM + n) = o0;
            *(float2*)(outf + (size_t)(m0 + 8) * DM + n) = o1;
        }
    }
}

// ---------------- kernel 3: split-K flash attention -------------------------
// grid (16, 32, 2): z = key half (1024 keys each). Stores RAW partial O (f16)
// and partial denominator lp; combine_kernel finishes the softmax + gate.
#define AK0 0
#define AV0 16384
#define AK1 32768      /* Q parked here initially */
#define AV1 49152      /* CQ parked here initially (2KB used) */
#define ACK0 65536
#define ACK1 67584
#define ASMEM 69760

__global__ __launch_bounds__(128, 3) void attn_hmma(
    const float* __restrict__ lam_ptr)
{
    extern __shared__ char smraw[];
    uint32_t sb = s2u(smraw);
    int tid = threadIdx.x, lane = tid & 31, w = tid >> 5;   // w: 0..3
    int bh = blockIdx.y;
    int h = bh & (NH - 1);
    int T0 = (bh >> 4) * SEQ;
    int q0 = blockIdx.x * 128;
    int zz = blockIdx.z;
    int kb0 = T0 + zz * (SEQ / 2);
    float laml2 = 0.5f * (*lam_ptr) * 1.44269504f;

    uint32_t Ks[2]  = {sb + AK0, sb + AK1};
    uint32_t Vs[2]  = {sb + AV0, sb + AV1};
    uint32_t CKs[2] = {sb + ACK0, sb + ACK1};
    uint32_t one_b = (lane < 4) ? 0x3C003C00u : 0u;   // f16 ones col (n=0)

    // prologue: Q -> AK1, K0 -> AK0, V0 -> AV0 (one cp.async group)
#pragma unroll
    for (int it = 0; it < 8; it++) {
        int i = tid + it * 128;
        int row = i >> 3, ch = i & 7;
        uint32_t so = SW(row * 128 + ch * 16);
        CPA(sb + AK1 + so, g_qb + (size_t)(T0 + q0 + row) * DM + h * DH + ch * 8);
        CPA(sb + AK0 + so, g_kb + (size_t)(kb0 + row) * DM + h * DH + ch * 8);
        CPA(sb + AV0 + so, g_vb + (size_t)(kb0 + row) * DM + h * DH + ch * 8);
    }
    CPCOMMIT();
    {   // CQ (f16, lam-scaled, 16B/row) into AV1 area; CK0 (f16)
        float2 cq = g_cs2[T0 + q0 + tid];
        uint32_t* d = (uint32_t*)(smraw + AV1 + tid * 16);
        d[0] = pkhf(laml2 * cq.x, laml2 * cq.y);
        d[1] = pkhf(laml2, 0.f);
        d[2] = 0; d[3] = 0;
        float2 ck = g_cs2[kb0 + tid];
        uint32_t* e = (uint32_t*)(smraw + ACK0 + tid * 16);
        e[0] = pkhf(ck.x, ck.y);
        e[1] = pkhf(1.f, 0.f);
        e[2] = 0; e[3] = 0;
    }
    CPWAIT0();
    __syncthreads();

    // Q (k16 x4) + CQ (k8 x2) fragments for both 16-row sets
    uint32_t qf[2][4][4];
    uint32_t qfr[2][2];
    {
        int lch = lane >> 4;
#pragma unroll
        for (int rs = 0; rs < 2; rs++) {
            int arow = w * 32 + rs * 16 + (lane & 15);
#pragma unroll
            for (int ks = 0; ks < 4; ks++)
                LDSM4(qf[rs][ks], sb + AK1 + SW(arow * 128 + (ks * 2 + lch) * 16));
            LDSM2(qfr[rs], sb + AV1 + arow * 16);
        }
    }
    __syncthreads();   // everyone done with Q/CQ before buf1 prefetch clobbers

    uint32_t oacc[2][8][2];
#pragma unroll
    for (int rs = 0; rs < 2; rs++)
#pragma unroll
        for (int j = 0; j < 8; j++) { oacc[rs][j][0] = 0; oacc[rs][j][1] = 0; }
    float lpacc[2][4];
#pragma unroll
    for (int rs = 0; rs < 2; rs++)
#pragma unroll
        for (int q = 0; q < 4; q++) lpacc[rs][q] = 0.f;

    for (int t = 0; t < 8; t++) {
        int buf = t & 1;
        if (t < 7) {
#pragma unroll
            for (int it = 0; it < 8; it++) {
                int i = tid + it * 128;
                int row = i >> 3, ch = i & 7;
                uint32_t so = SW(row * 128 + ch * 16);
                CPA(Ks[buf ^ 1] + so,
                    g_kb + (size_t)(kb0 + (t + 1) * 128 + row) * DM + h * DH + ch * 8);
                CPA(Vs[buf ^ 1] + so,
                    g_vb + (size_t)(kb0 + (t + 1) * 128 + row) * DM + h * DH + ch * 8);
            }
            CPCOMMIT();
            {
                float2 cs = g_cs2[kb0 + (t + 1) * 128 + tid];
                uint32_t* d = (uint32_t*)(smraw + (buf ? ACK0 : ACK1) + tid * 16);
                d[0] = pkhf(cs.x, cs.y);
                d[1] = pkhf(1.f, 0.f);
                d[2] = 0; d[3] = 0;
            }
            CPWAIT1();
        } else {
            CPWAIT0();
        }
        __syncthreads();

        int lch = lane >> 4;
#pragma unroll
        for (int t8 = 0; t8 < 8; t8++) {
            uint32_t sacc[2][2][2];
#pragma unroll
            for (int rs = 0; rs < 2; rs++) {
                sacc[rs][0][0] = 0; sacc[rs][0][1] = 0;
                sacc[rs][1][0] = 0; sacc[rs][1][1] = 0;
            }
#pragma unroll
            for (int ks = 0; ks < 4; ks++) {
                uint32_t b[4];
                LDSM4(b, Ks[buf] + SW((t8 * 16 + (lane & 15)) * 128 +
                                      (ks * 2 + lch) * 16));
                mmaf16(sacc[0][0], qf[0][ks], b[0], b[2]);
                mmaf16(sacc[0][1], qf[0][ks], b[1], b[3]);
                mmaf16(sacc[1][0], qf[1][ks], b[0], b[2]);
                mmaf16(sacc[1][1], qf[1][ks], b[1], b[3]);
            }
            {   // resonance k8 step (f16)
                uint32_t b[2];
                LDSM2(b, CKs[buf] + (t8 * 16 + (lane & 15)) * 16);
                mmaf16k8(sacc[0][0], qfr[0], b[0]);
                mmaf16k8(sacc[0][1], qfr[0], b[1]);
                mmaf16k8(sacc[1][0], qfr[1], b[0]);
                mmaf16k8(sacc[1][1], qfr[1], b[1]);
            }

            uint32_t pa[2][4];
#pragma unroll
            for (int rs = 0; rs < 2; rs++) {
                pa[rs][0] = ex2h2(sacc[rs][0][0]);
                pa[rs][1] = ex2h2(sacc[rs][0][1]);
                pa[rs][2] = ex2h2(sacc[rs][1][0]);
                pa[rs][3] = ex2h2(sacc[rs][1][1]);
            }
            mmaf16f32(lpacc[0], pa[0], one_b, one_b);
            mmaf16f32(lpacc[1], pa[1], one_b, one_b);
#pragma unroll
            for (int jt = 0; jt < 4; jt++) {
                uint32_t b[4];
                LDSM4T(b, Vs[buf] + SW((t8 * 16 + (lane & 15)) * 128 +
                                       (2 * jt + lch) * 16));
                mmaf16(oacc[0][2 * jt], pa[0], b[0], b[1]);
                mmaf16(oacc[0][2 * jt + 1], pa[0], b[2], b[3]);
                mmaf16(oacc[1][2 * jt], pa[1], b[0], b[1]);
                mmaf16(oacc[1][2 * jt + 1], pa[1], b[2], b[3]);
            }
        }
        __syncthreads();
    }

    // store RAW partial O + partial lp (combine kernel normalizes/gates)
    int c0 = (lane & 3) * 2;
    __half* opz = g_op + (size_t)zz * TOK * DM;
    float* lpz = g_lpg + (size_t)zz * TOK * NH;
#pragma unroll
    for (int rs = 0; rs < 2; rs++) {
        int r0g = T0 + q0 + w * 32 + rs * 16 + (lane >> 2);
        int r1g = r0g + 8;
        if ((lane & 3) == 0) {
            lpz[r0g * NH + h] = lpacc[rs][0];
            lpz[r1g * NH + h] = lpacc[rs][2];
        }
#pragma unroll
        for (int jt = 0; jt < 8; jt++) {
            int d = h * DH + jt * 8 + c0;
            *(uint32_t*)(opz + (size_t)r0g * DM + d) = oacc[rs][jt][0];
            *(uint32_t*)(opz + (size_t)r1g * DM + d) = oacc[rs][jt][1];
        }
    }
}

// ---------------- kernel 3b: split-K combine + gate + energy ----------------
__global__ __launch_bounds__(256) void combine_kernel(float* __restrict__ energy)
{
    int row = blockIdx.x, tid = threadIdx.x;
    int h = tid >> 4;                       // tid*4 / 64
    float l = g_lpg[row * NH + h] + g_lpg[TOK * NH + row * NH + h];
    float inv = g_headT[row * NH + h] / l;

    const uint32_t* p0 = (const uint32_t*)(g_op + (size_t)row * DM) + tid * 2;
    const uint32_t* p1 = (const uint32_t*)(g_op + (size_t)(TOK + row) * DM) + tid * 2;
    uint32_t* dst = (uint32_t*)(g_ogh + (size_t)row * DM) + tid * 2;

    float es = 0.f;
#pragma unroll
    for (int k = 0; k < 2; k++) {
        float2 a = __half22float2(*(const __half2*)&p0[k]);
        float2 b = __half22float2(*(const __half2*)&p1[k]);
        float o0 = (a.x + b.x) * inv;
        float o1 = (a.y + b.y) * inv;
        es += fabsf(o0) + fabsf(o1);
        dst[k] = pkhf(o0, o1);
    }
#pragma unroll
    for (int o = 16; o; o >>= 1) es += __shfl_xor_sync(0xffffffffu, es, o);
    __shared__ float red[8];
    int warp = tid >> 5, lane = tid & 31;
    if (lane == 0) red[warp] = es;
    __syncthreads();
    if (tid == 0) {
        float t = 0.f;
#pragma unroll
        for (int i = 0; i < 8; i++) t += red[i];
        atomicAdd(energy, t);
    }
}

// ---------------- launch ---------------------------------------------------
extern "C" void kernel_launch(void* const* d_in, const int* in_sizes, int n_in,
                              void* d_out, int out_size)
{
    const float* x       = (const float*)d_in[0];
    const float* Wq      = (const float*)d_in[1];
    const float* Wk      = (const float*)d_in[2];
    const float* Wv      = (const float*)d_in[3];
    const float* Wo      = (const float*)d_in[4];
    const float* Wp      = (const float*)d_in[5];
    const float* gamma   = (const float*)d_in[6];
    const float* beta    = (const float*)d_in[7];
    const float* carrier = (const float*)d_in[8];
    const float* lam     = (const float*)d_in[9];

    float* out    = (float*)d_out;
    float* energy = out + (out_size - 1);

    cudaFuncSetAttribute(gemm_qkv, cudaFuncAttributeMaxDynamicSharedMemorySize, 98304);
    cudaFuncSetAttribute(gemm_out, cudaFuncAttributeMaxDynamicSharedMemorySize, 65536);
    cudaFuncSetAttribute(attn_hmma, cudaFuncAttributeMaxDynamicSharedMemorySize, ASMEM);

    prep_kernel<<<2 * TOK, 256>>>(x, gamma, beta, Wp, carrier, energy,
                                  Wq, Wk, Wv, Wo);
    gemm_qkv<<<dim3(8, 32, 2), 256, 98304>>>();
    attn_hmma<<<dim3(SEQ / 128, 2 * NH, 2), 128, ASMEM>>>(lam);
    combine_kernel<<<TOK, 256>>>(energy);
    gemm_out<<<dim3(8, 32), 256, 65536>>>(x, out);
}